// round 5
// baseline (speedup 1.0000x reference)
#include <cuda_runtime.h>
#include <math.h>

#define BB   128   // batch
#define TSEQ 512   // sequence length
#define DD   256   // model dim
#define HH   256   // lstm hidden
#define NG   1024  // 4*HH
#define NBLK 384   // persistent LSTM grid (6 layer-steps x 64 tiles)

typedef unsigned long long u64;

// ---- packed f32x2 helpers ----
__device__ __forceinline__ u64 pk2(float lo, float hi) {
    u64 r; asm("mov.b64 %0, {%1,%2};" : "=l"(r) : "f"(lo), "f"(hi)); return r;
}
__device__ __forceinline__ u64 ff2(u64 a, u64 b, u64 c) {
    u64 d; asm("fma.rn.f32x2 %0, %1, %2, %3;" : "=l"(d) : "l"(a), "l"(b), "l"(c));
    return d;
}
__device__ __forceinline__ float2 up2(u64 v) {
    float2 f; asm("mov.b64 {%0,%1}, %2;" : "=f"(f.x), "=f"(f.y) : "l"(v)); return f;
}

// ---------------- device scratch ----------------
__device__ float g_x[BB * TSEQ * DD];
__device__ float g_feats[BB * TSEQ * DD];
__device__ float g_Wt[2 * 3 * 512 * NG];       // [dl][k(512)][col*4+gate]  (undup)
__device__ float g_cur[2 * 2 * 2 * BB * DD];   // [dir][stage][parity][b][d]
__device__ float g_h[2 * 3 * 2 * BB * HH];     // [dl][pingpong][b][h]
__device__ float g_c[2 * 3 * BB * HH];
__device__ unsigned g_sync;

// ---------------- embedding gather ----------------
__global__ void k_embed(const int* __restrict__ tokens, const float* __restrict__ E) {
    int row = blockIdx.x;
    int tok = tokens[row];
    const float4* src = reinterpret_cast<const float4*>(E) + (size_t)tok * (DD / 4);
    float4* dst = reinterpret_cast<float4*>(g_x) + (size_t)row * (DD / 4);
    dst[threadIdx.x] = src[threadIdx.x];
}

// ---------------- conv bank (FFMA2, pre-paired x) ----------------
__global__ void __launch_bounds__(256, 2) k_conv(
    const float* __restrict__ W3, const float* __restrict__ W5,
    const float* __restrict__ W7, const float* __restrict__ bconv, int iter)
{
    const int o  = threadIdx.x;
    const int t0 = blockIdx.x * 16;
    const int b  = blockIdx.y;

    __shared__ u64 sxp[DD][15];   // [c][pair i] = {x[t0-3+i], x[t0+5+i]}
    const float* xb = g_x + (size_t)b * TSEQ * DD;
    float xr[22];
#pragma unroll
    for (int r = 0; r < 22; ++r) {
        int tg = t0 - 3 + r;
        xr[r] = (tg >= 0 && tg < TSEQ) ? xb[(size_t)tg * DD + o] : 0.f;
    }
#pragma unroll
    for (int i = 0; i < 14; ++i) sxp[o][i] = pk2(xr[i], xr[i + 8]);
    __syncthreads();

    u64 acc3[8], acc5[8], acc7[8];
    const u64 z = pk2(0.f, 0.f);
#pragma unroll
    for (int i = 0; i < 8; ++i) { acc3[i] = z; acc5[i] = z; acc7[i] = z; }

    const float* W3i = W3 + (size_t)iter * 3 * DD * DD + o;
    const float* W5i = W5 + (size_t)iter * 5 * DD * DD + o;
    const float* W7i = W7 + (size_t)iter * 7 * DD * DD + o;

    for (int c = 0; c < DD; ++c) {
        u64 xp[14];
#pragma unroll
        for (int i = 0; i < 14; ++i) xp[i] = sxp[c][i];

#pragma unroll
        for (int k = 0; k < 7; ++k) {
            float w = W7i[((size_t)k * DD + c) * DD];
            u64 ww = pk2(w, w);
#pragma unroll
            for (int i = 0; i < 8; ++i) acc7[i] = ff2(xp[i + k], ww, acc7[i]);
        }
#pragma unroll
        for (int k = 0; k < 5; ++k) {
            float w = W5i[((size_t)k * DD + c) * DD];
            u64 ww = pk2(w, w);
#pragma unroll
            for (int i = 0; i < 8; ++i) acc5[i] = ff2(xp[i + k + 1], ww, acc5[i]);
        }
#pragma unroll
        for (int k = 0; k < 3; ++k) {
            float w = W3i[((size_t)k * DD + c) * DD];
            u64 ww = pk2(w, w);
#pragma unroll
            for (int i = 0; i < 8; ++i) acc3[i] = ff2(xp[i + k + 2], ww, acc3[i]);
        }
    }

    float b3 = bconv[(iter * 3 + 0) * DD + o];
    float b5 = bconv[(iter * 3 + 1) * DD + o];
    float b7 = bconv[(iter * 3 + 2) * DD + o];
    float* fb = g_feats + ((size_t)b * TSEQ + t0) * DD + o;
#pragma unroll
    for (int i = 0; i < 8; ++i) {
        float2 a3 = up2(acc3[i]), a5 = up2(acc5[i]), a7 = up2(acc7[i]);
        float2 res = up2(sxp[o][i + 3]);
        fb[(size_t)i * DD] = tanhf(a3.x + b3) + tanhf(a5.x + b5) +
                             tanhf(a7.x + b7) + res.x;
        fb[(size_t)(i + 8) * DD] = tanhf(a3.y + b3) + tanhf(a5.y + b5) +
                                   tanhf(a7.y + b7) + res.y;
    }
}

// ---------------- layernorm ----------------
__global__ void k_ln(const float* __restrict__ gamma, const float* __restrict__ beta, int iter) {
    int wid = threadIdx.x >> 5, lane = threadIdx.x & 31;
    int row = blockIdx.x * 8 + wid;
    const float4* f = reinterpret_cast<const float4*>(g_feats + (size_t)row * DD);
    float4 v0 = f[lane];
    float4 v1 = f[32 + lane];
    float s = v0.x + v0.y + v0.z + v0.w + v1.x + v1.y + v1.z + v1.w;
    float q = v0.x*v0.x + v0.y*v0.y + v0.z*v0.z + v0.w*v0.w +
              v1.x*v1.x + v1.y*v1.y + v1.z*v1.z + v1.w*v1.w;
#pragma unroll
    for (int ofs = 16; ofs; ofs >>= 1) {
        s += __shfl_xor_sync(0xffffffffu, s, ofs);
        q += __shfl_xor_sync(0xffffffffu, q, ofs);
    }
    float mean = s * (1.f / 256.f);
    float var  = q * (1.f / 256.f) - mean * mean;
    float rstd = rsqrtf(var + 1e-3f);

    const float* ga = gamma + iter * DD;
    const float* be = beta + iter * DD;
    float4* xo = reinterpret_cast<float4*>(g_x + (size_t)row * DD);
    int c0 = lane * 4;
    float4 r0, r1;
    r0.x = (v0.x - mean) * rstd * ga[c0 + 0] + be[c0 + 0];
    r0.y = (v0.y - mean) * rstd * ga[c0 + 1] + be[c0 + 1];
    r0.z = (v0.z - mean) * rstd * ga[c0 + 2] + be[c0 + 2];
    r0.w = (v0.w - mean) * rstd * ga[c0 + 3] + be[c0 + 3];
    r1.x = (v1.x - mean) * rstd * ga[128 + c0 + 0] + be[128 + c0 + 0];
    r1.y = (v1.y - mean) * rstd * ga[128 + c0 + 1] + be[128 + c0 + 1];
    r1.z = (v1.z - mean) * rstd * ga[128 + c0 + 2] + be[128 + c0 + 2];
    r1.w = (v1.w - mean) * rstd * ga[128 + c0 + 3] + be[128 + c0 + 3];
    xo[lane] = r0;
    xo[32 + lane] = r1;
}

// ---------------- weight pre-transpose (undup): [dl][k][col*4+g] ----------------
__global__ void k_transpose(const float* __restrict__ Wx, const float* __restrict__ Wh) {
    int idx = blockIdx.x * 256 + threadIdx.x;
    if (idx >= 2 * 3 * 512 * NG) return;
    int dl  = idx / (512 * NG);
    int rem = idx % (512 * NG);
    int k   = rem / NG;
    int cp  = rem % NG;       // cp = col*4 + g
    int col = cp >> 2, g = cp & 3;
    int n = g * 256 + col;
    float v = (k < 256) ? Wx[(size_t)dl * 256 * NG + (size_t)k * NG + n]
                        : Wh[(size_t)dl * 256 * NG + (size_t)(k - 256) * NG + n];
    g_Wt[idx] = v;
}

__global__ void k_zero() {
    int i = blockIdx.x * 256 + threadIdx.x;
    if (i < 2 * 3 * 2 * BB * HH) g_h[i] = 0.f;
    if (i < 2 * 3 * BB * HH)     g_c[i] = 0.f;
    if (i == 0) g_sync = 0u;
}

// ---------------- persistent wavefront LSTM (gate-paired FFMA2, dup-A) -----
// 384 blocks x 128 threads. Block tile 32m x 16 cols (x4 gates).
// Thread: j = tid&15 (col), mg = tid>>4 (4 m-rows). 11 issues / 16 FMA-cyc per k.
__global__ void __launch_bounds__(128, 3) k_lstm_persist(
    const float* __restrict__ blstm, float* __restrict__ out)
{
    const int bx    = blockIdx.x;
    const int ls    = bx >> 6;
    const int dir   = ls & 1;
    const int layer = ls >> 1;
    const int sub   = bx & 63;
    const int j0    = (sub & 15) * 16;
    const int m0    = (sub >> 4) * 32;
    const int tid   = threadIdx.x;
    const int j     = tid & 15;          // col within tile
    const int mg    = tid >> 4;          // 0..7 -> rows m0+mg*4..+3
    const int dl    = dir * 3 + layer;

    __shared__ float sAd[32][68];    // [k][2m dup], row 272B (16B aligned)
    __shared__ float sW[32][64];     // [k][col*4+g]

    const float* Wl = g_Wt + (size_t)dl * 512 * NG + j0 * 4;
    const int col = j0 + j;
    const float* bbias = blstm + (size_t)dl * NG;
    const float bi  = bbias[col];
    const float bf_ = bbias[256 + col];
    const float bg  = bbias[512 + col];
    const float bo  = bbias[768 + col];
    float* cbuf = g_c + (size_t)dl * BB * HH;

    // fill roles: each thread loads 8 consecutive k for one m
    const int fm = tid >> 2;          // 0..31 row within tile
    const int fk = (tid & 3) * 8;     // k base within chunk

    const unsigned nb = gridDim.x;
    const int lprev = (layer > 0) ? (layer - 1) : 0;

    for (int w = 0; w < TSEQ + 2; ++w) {
        const int t = w - layer;
        if (t >= 0 && t < TSEQ) {
            const int tt = dir ? (TSEQ - 1 - t) : t;
            const int rp = t & 1, wp = rp ^ 1;
            const float* hin = g_h + (size_t)(dl * 2 + rp) * BB * HH;
            const float* cursrc = g_cur +
                (size_t)((dir * 2 + lprev) * 2 + (t & 1)) * BB * DD;
            float* curdst = g_cur +
                (size_t)((dir * 2 + layer) * 2 + (t & 1)) * BB * DD;

            u64 acc[4][2];                    // [m][gatepair]
            const u64 zz = pk2(0.f, 0.f);
#pragma unroll
            for (int g = 0; g < 4; ++g) { acc[g][0] = zz; acc[g][1] = zz; }

            for (int kc = 0; kc < 512; kc += 32) {
                // --- fill sAd (duplicated activation) ---
                {
                    int m = m0 + fm;
                    int kk = kc + fk;
                    float4 v0, v1;
                    if (kk < 256) {
                        const float* src = (layer == 0)
                            ? (g_x + ((size_t)m * TSEQ + tt) * DD + kk)
                            : (cursrc + (size_t)m * DD + kk);
                        v0 = *reinterpret_cast<const float4*>(src);
                        v1 = *reinterpret_cast<const float4*>(src + 4);
                    } else {
                        const float* src = hin + (size_t)m * HH + (kk - 256);
                        v0 = __ldcg(reinterpret_cast<const float4*>(src));
                        v1 = __ldcg(reinterpret_cast<const float4*>(src) + 1);
                    }
                    *reinterpret_cast<u64*>(&sAd[fk + 0][fm * 2]) = pk2(v0.x, v0.x);
                    *reinterpret_cast<u64*>(&sAd[fk + 1][fm * 2]) = pk2(v0.y, v0.y);
                    *reinterpret_cast<u64*>(&sAd[fk + 2][fm * 2]) = pk2(v0.z, v0.z);
                    *reinterpret_cast<u64*>(&sAd[fk + 3][fm * 2]) = pk2(v0.w, v0.w);
                    *reinterpret_cast<u64*>(&sAd[fk + 4][fm * 2]) = pk2(v1.x, v1.x);
                    *reinterpret_cast<u64*>(&sAd[fk + 5][fm * 2]) = pk2(v1.y, v1.y);
                    *reinterpret_cast<u64*>(&sAd[fk + 6][fm * 2]) = pk2(v1.z, v1.z);
                    *reinterpret_cast<u64*>(&sAd[fk + 7][fm * 2]) = pk2(v1.w, v1.w);
                }
                // --- fill sW (undup: 32k x 64 floats) ---
#pragma unroll
                for (int r = 0; r < 4; ++r) {
                    int e4 = tid + r * 128;
                    int k = e4 >> 4, c4 = e4 & 15;
                    *reinterpret_cast<float4*>(&sW[k][c4 * 4]) =
                        *reinterpret_cast<const float4*>(&Wl[(size_t)(kc + k) * NG + c4 * 4]);
                }
                __syncthreads();
                // --- compute: 3 LDS.128 + 8 FFMA2 per k ---
#pragma unroll
                for (int k = 0; k < 32; ++k) {
                    ulonglong2 aa = *reinterpret_cast<const ulonglong2*>(&sAd[k][mg * 8]);
                    ulonglong2 ab = *reinterpret_cast<const ulonglong2*>(&sAd[k][mg * 8 + 4]);
                    ulonglong2 wv = *reinterpret_cast<const ulonglong2*>(&sW[k][j * 4]);
                    acc[0][0] = ff2(aa.x, wv.x, acc[0][0]);
                    acc[0][1] = ff2(aa.x, wv.y, acc[0][1]);
                    acc[1][0] = ff2(aa.y, wv.x, acc[1][0]);
                    acc[1][1] = ff2(aa.y, wv.y, acc[1][1]);
                    acc[2][0] = ff2(ab.x, wv.x, acc[2][0]);
                    acc[2][1] = ff2(ab.x, wv.y, acc[2][1]);
                    acc[3][0] = ff2(ab.y, wv.x, acc[3][0]);
                    acc[3][1] = ff2(ab.y, wv.y, acc[3][1]);
                }
                __syncthreads();
            }

            float* hout = g_h + (size_t)(dl * 2 + wp) * BB * HH;
#pragma unroll
            for (int mi = 0; mi < 4; ++mi) {
                int m = m0 + mg * 4 + mi;
                float2 zif = up2(acc[mi][0]);     // (z_i, z_f)
                float2 zgo = up2(acc[mi][1]);     // (z_g, z_o)
                float vzi = zif.x + bi;
                float vzf = zif.y + bf_;
                float vzg = zgo.x + bg;
                float vzo = zgo.y + bo;
                float ig = 1.f / (1.f + expf(-vzi));
                float fg = 1.f / (1.f + expf(-vzf));
                float gg = tanhf(vzg);
                float og = 1.f / (1.f + expf(-vzo));
                float cp = cbuf[(size_t)m * HH + col];
                float cn = fg * cp + ig * gg;
                float hn = og * tanhf(cn);
                cbuf[(size_t)m * HH + col] = cn;
                hout[(size_t)m * HH + col] = hn;
                float ain = (layer == 0)
                    ? g_x[((size_t)m * TSEQ + tt) * DD + col]
                    : __ldcg(cursrc + (size_t)m * DD + col);
                float cu = ain + hn;
                if (layer == 2)
                    out[((size_t)m * TSEQ + tt) * 512 + dir * 256 + col] = cu;
                else
                    curdst[(size_t)m * DD + col] = cu;
            }
        }

        // ---- grid barrier (proven R3 form) ----
        __syncthreads();
        __threadfence();
        if (tid == 0) {
            atomicAdd(&g_sync, 1u);
            unsigned target = nb * (unsigned)(w + 1);
            while (*(volatile unsigned*)&g_sync < target) __nanosleep(64);
        }
        __syncthreads();
    }
}

// ---------------- final states ----------------
__global__ void k_states(float* __restrict__ out) {
    int idx = blockIdx.x * 256 + threadIdx.x;
    if (idx >= 2 * 3 * BB * HH) return;
    int j  = idx & 255;
    int m  = (idx >> 8) & 127;
    int dl = idx >> 15;
    const size_t SEQ = (size_t)BB * TSEQ * 512;
    const size_t SH  = 2 * 3 * BB * HH;
    out[SEQ + idx]      = g_h[(size_t)(dl * 2 + 0) * BB * HH + (size_t)m * HH + j];
    out[SEQ + SH + idx] = g_c[(size_t)dl * BB * HH + (size_t)m * HH + j];
}

// ---------------- launch ----------------
extern "C" void kernel_launch(void* const* d_in, const int* in_sizes, int n_in,
                              void* d_out, int out_size) {
    const int*   tokens = (const int*)d_in[0];
    const float* E      = (const float*)d_in[1];
    const float* W3     = (const float*)d_in[2];
    const float* W5     = (const float*)d_in[3];
    const float* W7     = (const float*)d_in[4];
    const float* bconv  = (const float*)d_in[5];
    const float* gamma  = (const float*)d_in[6];
    const float* beta   = (const float*)d_in[7];
    const float* Wx     = (const float*)d_in[8];
    const float* Wh     = (const float*)d_in[9];
    const float* blstm  = (const float*)d_in[10];
    float* out = (float*)d_out;

    k_embed<<<BB * TSEQ, 64>>>(tokens, E);
    for (int it = 0; it < 2; ++it) {
        k_conv<<<dim3(TSEQ / 16, BB), 256>>>(W3, W5, W7, bconv, it);
        k_ln<<<BB * TSEQ / 8, 256>>>(gamma, beta, it);
    }
    k_transpose<<<(2 * 3 * 512 * NG + 255) / 256, 256>>>(Wx, Wh);
    k_zero<<<1536, 256>>>();
    k_lstm_persist<<<NBLK, 128>>>(blstm, out);
    k_states<<<768, 256>>>(out);
}

// round 6
// speedup vs baseline: 1.2411x; 1.2411x over previous
#include <cuda_runtime.h>
#include <math.h>

#define BB   128   // batch
#define TSEQ 512   // sequence length
#define DD   256   // model dim
#define HH   256   // lstm hidden
#define NG   1024  // 4*HH
#define NBLK 96    // persistent LSTM grid: 6 layer-steps x 16 col-tiles

typedef unsigned long long u64;

// ---- packed f32x2 helpers ----
__device__ __forceinline__ u64 pk2(float lo, float hi) {
    u64 r; asm("mov.b64 %0, {%1,%2};" : "=l"(r) : "f"(lo), "f"(hi)); return r;
}
__device__ __forceinline__ u64 ff2(u64 a, u64 b, u64 c) {
    u64 d; asm("fma.rn.f32x2 %0, %1, %2, %3;" : "=l"(d) : "l"(a), "l"(b), "l"(c));
    return d;
}
__device__ __forceinline__ float2 up2(u64 v) {
    float2 f; asm("mov.b64 {%0,%1}, %2;" : "=f"(f.x), "=f"(f.y) : "l"(v)); return f;
}

// ---------------- device scratch ----------------
__device__ float g_x[BB * TSEQ * DD];
__device__ float g_feats[BB * TSEQ * DD];
__device__ float g_Wt[2 * 3 * 512 * NG];       // [dl][k(512)][col*4+gate]
__device__ float g_cur[2 * 2 * 2 * BB * DD];   // [dir][stage][parity][b][d]
__device__ float g_h[2 * 3 * 2 * BB * HH];     // [dl][pingpong][b][h]
__device__ float g_c[2 * 3 * BB * HH];
__device__ unsigned g_sync;

// ---------------- embedding gather ----------------
__global__ void k_embed(const int* __restrict__ tokens, const float* __restrict__ E) {
    int row = blockIdx.x;
    int tok = tokens[row];
    const float4* src = reinterpret_cast<const float4*>(E) + (size_t)tok * (DD / 4);
    float4* dst = reinterpret_cast<float4*>(g_x) + (size_t)row * (DD / 4);
    dst[threadIdx.x] = src[threadIdx.x];
}

// ---------------- conv bank (FFMA2, pre-paired x) — unchanged (fastest) ----
__global__ void __launch_bounds__(256, 2) k_conv(
    const float* __restrict__ W3, const float* __restrict__ W5,
    const float* __restrict__ W7, const float* __restrict__ bconv, int iter)
{
    const int o  = threadIdx.x;
    const int t0 = blockIdx.x * 16;
    const int b  = blockIdx.y;

    __shared__ u64 sxp[DD][15];
    const float* xb = g_x + (size_t)b * TSEQ * DD;
    float xr[22];
#pragma unroll
    for (int r = 0; r < 22; ++r) {
        int tg = t0 - 3 + r;
        xr[r] = (tg >= 0 && tg < TSEQ) ? xb[(size_t)tg * DD + o] : 0.f;
    }
#pragma unroll
    for (int i = 0; i < 14; ++i) sxp[o][i] = pk2(xr[i], xr[i + 8]);
    __syncthreads();

    u64 acc3[8], acc5[8], acc7[8];
    const u64 z = pk2(0.f, 0.f);
#pragma unroll
    for (int i = 0; i < 8; ++i) { acc3[i] = z; acc5[i] = z; acc7[i] = z; }

    const float* W3i = W3 + (size_t)iter * 3 * DD * DD + o;
    const float* W5i = W5 + (size_t)iter * 5 * DD * DD + o;
    const float* W7i = W7 + (size_t)iter * 7 * DD * DD + o;

    for (int c = 0; c < DD; ++c) {
        u64 xp[14];
#pragma unroll
        for (int i = 0; i < 14; ++i) xp[i] = sxp[c][i];

#pragma unroll
        for (int k = 0; k < 7; ++k) {
            float w = W7i[((size_t)k * DD + c) * DD];
            u64 ww = pk2(w, w);
#pragma unroll
            for (int i = 0; i < 8; ++i) acc7[i] = ff2(xp[i + k], ww, acc7[i]);
        }
#pragma unroll
        for (int k = 0; k < 5; ++k) {
            float w = W5i[((size_t)k * DD + c) * DD];
            u64 ww = pk2(w, w);
#pragma unroll
            for (int i = 0; i < 8; ++i) acc5[i] = ff2(xp[i + k + 1], ww, acc5[i]);
        }
#pragma unroll
        for (int k = 0; k < 3; ++k) {
            float w = W3i[((size_t)k * DD + c) * DD];
            u64 ww = pk2(w, w);
#pragma unroll
            for (int i = 0; i < 8; ++i) acc3[i] = ff2(xp[i + k + 2], ww, acc3[i]);
        }
    }

    float b3 = bconv[(iter * 3 + 0) * DD + o];
    float b5 = bconv[(iter * 3 + 1) * DD + o];
    float b7 = bconv[(iter * 3 + 2) * DD + o];
    float* fb = g_feats + ((size_t)b * TSEQ + t0) * DD + o;
#pragma unroll
    for (int i = 0; i < 8; ++i) {
        float2 a3 = up2(acc3[i]), a5 = up2(acc5[i]), a7 = up2(acc7[i]);
        float2 res = up2(sxp[o][i + 3]);
        fb[(size_t)i * DD] = tanhf(a3.x + b3) + tanhf(a5.x + b5) +
                             tanhf(a7.x + b7) + res.x;
        fb[(size_t)(i + 8) * DD] = tanhf(a3.y + b3) + tanhf(a5.y + b5) +
                                   tanhf(a7.y + b7) + res.y;
    }
}

// ---------------- layernorm ----------------
__global__ void k_ln(const float* __restrict__ gamma, const float* __restrict__ beta, int iter) {
    int wid = threadIdx.x >> 5, lane = threadIdx.x & 31;
    int row = blockIdx.x * 8 + wid;
    const float4* f = reinterpret_cast<const float4*>(g_feats + (size_t)row * DD);
    float4 v0 = f[lane];
    float4 v1 = f[32 + lane];
    float s = v0.x + v0.y + v0.z + v0.w + v1.x + v1.y + v1.z + v1.w;
    float q = v0.x*v0.x + v0.y*v0.y + v0.z*v0.z + v0.w*v0.w +
              v1.x*v1.x + v1.y*v1.y + v1.z*v1.z + v1.w*v1.w;
#pragma unroll
    for (int ofs = 16; ofs; ofs >>= 1) {
        s += __shfl_xor_sync(0xffffffffu, s, ofs);
        q += __shfl_xor_sync(0xffffffffu, q, ofs);
    }
    float mean = s * (1.f / 256.f);
    float var  = q * (1.f / 256.f) - mean * mean;
    float rstd = rsqrtf(var + 1e-3f);

    const float* ga = gamma + iter * DD;
    const float* be = beta + iter * DD;
    float4* xo = reinterpret_cast<float4*>(g_x + (size_t)row * DD);
    int c0 = lane * 4;
    float4 r0, r1;
    r0.x = (v0.x - mean) * rstd * ga[c0 + 0] + be[c0 + 0];
    r0.y = (v0.y - mean) * rstd * ga[c0 + 1] + be[c0 + 1];
    r0.z = (v0.z - mean) * rstd * ga[c0 + 2] + be[c0 + 2];
    r0.w = (v0.w - mean) * rstd * ga[c0 + 3] + be[c0 + 3];
    r1.x = (v1.x - mean) * rstd * ga[128 + c0 + 0] + be[128 + c0 + 0];
    r1.y = (v1.y - mean) * rstd * ga[128 + c0 + 1] + be[128 + c0 + 1];
    r1.z = (v1.z - mean) * rstd * ga[128 + c0 + 2] + be[128 + c0 + 2];
    r1.w = (v1.w - mean) * rstd * ga[128 + c0 + 3] + be[128 + c0 + 3];
    xo[lane] = r0;
    xo[32 + lane] = r1;
}

// ---------------- weight pre-transpose: [dl][k][col*4+g] ----------------
__global__ void k_transpose(const float* __restrict__ Wx, const float* __restrict__ Wh) {
    int idx = blockIdx.x * 256 + threadIdx.x;
    if (idx >= 2 * 3 * 512 * NG) return;
    int dl  = idx / (512 * NG);
    int rem = idx % (512 * NG);
    int k   = rem / NG;
    int cp  = rem % NG;
    int col = cp >> 2, g = cp & 3;
    int n = g * 256 + col;
    float v = (k < 256) ? Wx[(size_t)dl * 256 * NG + (size_t)k * NG + n]
                        : Wh[(size_t)dl * 256 * NG + (size_t)(k - 256) * NG + n];
    g_Wt[idx] = v;
}

__global__ void k_zero() {
    int i = blockIdx.x * 256 + threadIdx.x;
    if (i < 2 * 3 * 2 * BB * HH) g_h[i] = 0.f;
    if (i < 2 * 3 * BB * HH)     g_c[i] = 0.f;
    if (i == 0) g_sync = 0u;
}

// ---------------- persistent wavefront LSTM, W resident in SMEM ----------
// 96 blocks x 256 threads, 1 block/SM. Block: all 128 m x 16 cols (x4 gates).
// W slice 512x64 floats = 128KB loaded into smem ONCE. A double-buffered with
// register prefetch: one syncthreads per 32-k chunk, zero W traffic in loop.
#define APITCH 130
__global__ void __launch_bounds__(256, 1) k_lstm_persist(
    const float* __restrict__ blstm, float* __restrict__ out)
{
    extern __shared__ float smem[];
    float* sWr = smem;                         // [512][64]      128 KB
    float* sA  = smem + 512 * 64;              // [2][32][APITCH] 33.3 KB

    const int bx    = blockIdx.x;
    const int ls    = bx >> 4;            // 0..5
    const int dir   = ls & 1;
    const int layer = ls >> 1;
    const int sub   = bx & 15;
    const int j0    = sub * 16;           // col tile base (16 cols)
    const int tid   = threadIdx.x;
    const int jc    = tid & 15;           // col within tile
    const int mq    = tid >> 4;           // 0..15 -> 8 m-rows each
    const int dl    = dir * 3 + layer;

    // ---- load W slice into smem once ----
    {
        const float4* src = reinterpret_cast<const float4*>(
            g_Wt + (size_t)dl * 512 * NG);
        float4* dst = reinterpret_cast<float4*>(sWr);
        // row k: 16 float4 of our 64 cols at offset k*256 + j0
        for (int i = tid; i < 512 * 16; i += 256) {
            int k = i >> 4, q = i & 15;
            dst[k * 16 + q] = src[(size_t)k * 256 + j0 + q];
        }
    }

    const int col = j0 + jc;
    const float* bbias = blstm + (size_t)dl * NG;
    const float bi  = bbias[col];
    const float bf_ = bbias[256 + col];
    const float bg  = bbias[512 + col];
    const float bo  = bbias[768 + col];
    float* cbuf = g_c + (size_t)dl * BB * HH;

    // A-fill roles: thread -> (row ftm, k-offset ffk), 16 floats each
    const int ftm = tid >> 1;             // 0..127 m row
    const int ffk = (tid & 1) * 16;       // k offset 0 / 16

    const unsigned nb = gridDim.x;
    const int lprev = (layer > 0) ? (layer - 1) : 0;

    for (int w = 0; w < TSEQ + 2; ++w) {
        const int t = w - layer;
        if (t >= 0 && t < TSEQ) {
            const int tt = dir ? (TSEQ - 1 - t) : t;
            const int rp = t & 1, wp = rp ^ 1;
            const float* hin = g_h + (size_t)(dl * 2 + rp) * BB * HH;
            const float* cursrc = g_cur +
                (size_t)((dir * 2 + lprev) * 2 + (t & 1)) * BB * DD;
            float* curdst = g_cur +
                (size_t)((dir * 2 + layer) * 2 + (t & 1)) * BB * DD;

            u64 acc[4][4];                 // [gate][m-pair]
            const u64 zz = pk2(0.f, 0.f);
#pragma unroll
            for (int g = 0; g < 4; ++g)
#pragma unroll
                for (int p = 0; p < 4; ++p) acc[g][p] = zz;

            // prefetch chunk 0
            float4 va[4];
            {
                const float* src = (layer == 0)
                    ? (g_x + ((size_t)ftm * TSEQ + tt) * DD + ffk)
                    : (cursrc + (size_t)ftm * DD + ffk);
#pragma unroll
                for (int i = 0; i < 4; ++i)
                    va[i] = *reinterpret_cast<const float4*>(src + i * 4);
            }
            // stage chunk 0
            {
                float* dstbuf = sA;  // buf 0
#pragma unroll
                for (int i = 0; i < 4; ++i) {
                    dstbuf[(ffk + i * 4 + 0) * APITCH + ftm] = va[i].x;
                    dstbuf[(ffk + i * 4 + 1) * APITCH + ftm] = va[i].y;
                    dstbuf[(ffk + i * 4 + 2) * APITCH + ftm] = va[i].z;
                    dstbuf[(ffk + i * 4 + 3) * APITCH + ftm] = va[i].w;
                }
            }
            __syncthreads();

            for (int ci = 0; ci < 16; ++ci) {
                // prefetch next chunk into regs
                if (ci < 15) {
                    int kk = (ci + 1) * 32 + ffk;
                    const float* src;
                    if (kk < 256) {
                        src = (layer == 0)
                            ? (g_x + ((size_t)ftm * TSEQ + tt) * DD + kk)
                            : (cursrc + (size_t)ftm * DD + kk);
#pragma unroll
                        for (int i = 0; i < 4; ++i)
                            va[i] = *reinterpret_cast<const float4*>(src + i * 4);
                    } else {
                        src = hin + (size_t)ftm * HH + (kk - 256);
#pragma unroll
                        for (int i = 0; i < 4; ++i)
                            va[i] = __ldcg(reinterpret_cast<const float4*>(src) + i);
                    }
                }

                // compute current chunk from sA[ci&1], W from resident sWr
                const float* ab = sA + (ci & 1) * (32 * APITCH);
                const float* wb = sWr + (size_t)ci * 32 * 64 + jc * 4;
#pragma unroll
                for (int k = 0; k < 32; ++k) {
                    const float* ar = ab + k * APITCH + mq * 8;
                    u64 a0 = *reinterpret_cast<const u64*>(ar + 0);
                    u64 a1 = *reinterpret_cast<const u64*>(ar + 2);
                    u64 a2 = *reinterpret_cast<const u64*>(ar + 4);
                    u64 a3 = *reinterpret_cast<const u64*>(ar + 6);
                    float4 wv = *reinterpret_cast<const float4*>(wb + k * 64);
                    u64 w0 = pk2(wv.x, wv.x);
                    u64 w1 = pk2(wv.y, wv.y);
                    u64 w2 = pk2(wv.z, wv.z);
                    u64 w3 = pk2(wv.w, wv.w);
                    acc[0][0] = ff2(a0, w0, acc[0][0]); acc[0][1] = ff2(a1, w0, acc[0][1]);
                    acc[0][2] = ff2(a2, w0, acc[0][2]); acc[0][3] = ff2(a3, w0, acc[0][3]);
                    acc[1][0] = ff2(a0, w1, acc[1][0]); acc[1][1] = ff2(a1, w1, acc[1][1]);
                    acc[1][2] = ff2(a2, w1, acc[1][2]); acc[1][3] = ff2(a3, w1, acc[1][3]);
                    acc[2][0] = ff2(a0, w2, acc[2][0]); acc[2][1] = ff2(a1, w2, acc[2][1]);
                    acc[2][2] = ff2(a2, w2, acc[2][2]); acc[2][3] = ff2(a3, w2, acc[2][3]);
                    acc[3][0] = ff2(a0, w3, acc[3][0]); acc[3][1] = ff2(a1, w3, acc[3][1]);
                    acc[3][2] = ff2(a2, w3, acc[3][2]); acc[3][3] = ff2(a3, w3, acc[3][3]);
                }

                // stage prefetched chunk into other buffer, then sync
                if (ci < 15) {
                    float* dstbuf = sA + ((ci + 1) & 1) * (32 * APITCH);
#pragma unroll
                    for (int i = 0; i < 4; ++i) {
                        dstbuf[(ffk + i * 4 + 0) * APITCH + ftm] = va[i].x;
                        dstbuf[(ffk + i * 4 + 1) * APITCH + ftm] = va[i].y;
                        dstbuf[(ffk + i * 4 + 2) * APITCH + ftm] = va[i].z;
                        dstbuf[(ffk + i * 4 + 3) * APITCH + ftm] = va[i].w;
                    }
                    __syncthreads();
                }
            }

            float* hout = g_h + (size_t)(dl * 2 + wp) * BB * HH;
#pragma unroll
            for (int p = 0; p < 4; ++p) {
                float2 zi = up2(acc[0][p]);
                float2 zf = up2(acc[1][p]);
                float2 zg = up2(acc[2][p]);
                float2 zo = up2(acc[3][p]);
#pragma unroll
                for (int h2 = 0; h2 < 2; ++h2) {
                    int m = mq * 8 + p * 2 + h2;
                    float vzi = (h2 ? zi.y : zi.x) + bi;
                    float vzf = (h2 ? zf.y : zf.x) + bf_;
                    float vzg = (h2 ? zg.y : zg.x) + bg;
                    float vzo = (h2 ? zo.y : zo.x) + bo;
                    float ig = 1.f / (1.f + expf(-vzi));
                    float fg = 1.f / (1.f + expf(-vzf));
                    float gg = tanhf(vzg);
                    float og = 1.f / (1.f + expf(-vzo));
                    float cp = cbuf[(size_t)m * HH + col];
                    float cn = fg * cp + ig * gg;
                    float hn = og * tanhf(cn);
                    cbuf[(size_t)m * HH + col] = cn;
                    hout[(size_t)m * HH + col] = hn;
                    float ain = (layer == 0)
                        ? g_x[((size_t)m * TSEQ + tt) * DD + col]
                        : __ldcg(cursrc + (size_t)m * DD + col);
                    float cu = ain + hn;
                    if (layer == 2)
                        out[((size_t)m * TSEQ + tt) * 512 + dir * 256 + col] = cu;
                    else
                        curdst[(size_t)m * DD + col] = cu;
                }
            }
        }

        // ---- grid barrier ----
        __syncthreads();
        __threadfence();
        if (tid == 0) {
            atomicAdd(&g_sync, 1u);
            unsigned target = nb * (unsigned)(w + 1);
            while (*(volatile unsigned*)&g_sync < target) __nanosleep(64);
        }
        __syncthreads();
    }
}

// ---------------- final states ----------------
__global__ void k_states(float* __restrict__ out) {
    int idx = blockIdx.x * 256 + threadIdx.x;
    if (idx >= 2 * 3 * BB * HH) return;
    int j  = idx & 255;
    int m  = (idx >> 8) & 127;
    int dl = idx >> 15;
    const size_t SEQ = (size_t)BB * TSEQ * 512;
    const size_t SH  = 2 * 3 * BB * HH;
    out[SEQ + idx]      = g_h[(size_t)(dl * 2 + 0) * BB * HH + (size_t)m * HH + j];
    out[SEQ + SH + idx] = g_c[(size_t)dl * BB * HH + (size_t)m * HH + j];
}

// ---------------- launch ----------------
extern "C" void kernel_launch(void* const* d_in, const int* in_sizes, int n_in,
                              void* d_out, int out_size) {
    const int*   tokens = (const int*)d_in[0];
    const float* E      = (const float*)d_in[1];
    const float* W3     = (const float*)d_in[2];
    const float* W5     = (const float*)d_in[3];
    const float* W7     = (const float*)d_in[4];
    const float* bconv  = (const float*)d_in[5];
    const float* gamma  = (const float*)d_in[6];
    const float* beta   = (const float*)d_in[7];
    const float* Wx     = (const float*)d_in[8];
    const float* Wh     = (const float*)d_in[9];
    const float* blstm  = (const float*)d_in[10];
    float* out = (float*)d_out;

    const int SMEM_BYTES = (512 * 64 + 2 * 32 * APITCH) * 4;   // 164,352 B
    static int s_attr_done = 0;
    if (!s_attr_done) {
        cudaFuncSetAttribute(k_lstm_persist,
                             cudaFuncAttributeMaxDynamicSharedMemorySize,
                             SMEM_BYTES);
        s_attr_done = 1;
    }

    k_embed<<<BB * TSEQ, 64>>>(tokens, E);
    for (int it = 0; it < 2; ++it) {
        k_conv<<<dim3(TSEQ / 16, BB), 256>>>(W3, W5, W7, bconv, it);
        k_ln<<<BB * TSEQ / 8, 256>>>(gamma, beta, it);
    }
    k_transpose<<<(2 * 3 * 512 * NG + 255) / 256, 256>>>(Wx, Wh);
    k_zero<<<1536, 256>>>();
    k_lstm_persist<<<NBLK, 256, SMEM_BYTES>>>(blstm, out);
    k_states<<<768, 256>>>(out);
}